// round 6
// baseline (speedup 1.0000x reference)
#include <cuda_runtime.h>
#include <cuda_fp16.h>
#include <cstdint>

#define BB 64
#define TT 1024
#define II 512
#define HH 512
#define MM (BB*TT)              // 65536

#define NGROUP 8                // batch groups for GEMM->scan pipelining
#define GB     (BB / NGROUP)    // 8 batches per group
#define GMT    (GB * TT / 128)  // 64 m-tiles per group

#define ALPHA_LO 0.8187307530779818f   // exp(-1/5)
#define ALPHA_HI 0.9607894391523232f   // exp(-1/25)

// Device-global scratch (allocation-guard safe)
__device__ float  g_wx[(size_t)MM * HH];        // 128 MB
__device__ __half g_bh[(size_t)HH * II];        // 512 KB (2048*W) high
__device__ __half g_bl[(size_t)HH * II];        // 512 KB (2048*W) low

// ---------------------------------------------------------------------------
__device__ __forceinline__ uint32_t smem_u32(const void* p) {
    uint32_t a;
    asm("{ .reg .u64 t; cvta.to.shared.u64 t, %1; cvt.u32.u64 %0, t; }" : "=r"(a) : "l"(p));
    return a;
}
__device__ __forceinline__ void cp16(uint32_t dst, const void* src) {
    asm volatile("cp.async.cg.shared.global [%0], [%1], 16;" :: "r"(dst), "l"(src));
}
__device__ __forceinline__ void ldsm_x4(uint32_t* r, uint32_t addr) {
    asm volatile("ldmatrix.sync.aligned.m8n8.x4.shared.b16 {%0,%1,%2,%3}, [%4];"
                 : "=r"(r[0]), "=r"(r[1]), "=r"(r[2]), "=r"(r[3]) : "r"(addr));
}
__device__ __forceinline__ void mma16816(float* c, const uint32_t* a, uint32_t b0, uint32_t b1) {
    asm volatile(
        "mma.sync.aligned.m16n8k16.row.col.f32.f16.f16.f32 "
        "{%0,%1,%2,%3}, {%4,%5,%6,%7}, {%8,%9}, {%0,%1,%2,%3};"
        : "+f"(c[0]), "+f"(c[1]), "+f"(c[2]), "+f"(c[3])
        : "r"(a[0]), "r"(a[1]), "r"(a[2]), "r"(a[3]), "r"(b0), "r"(b1));
}
__device__ __forceinline__ uint32_t h2bits(__half2 h) {
    return *reinterpret_cast<uint32_t*>(&h);
}

// ---------------------------------------------------------------------------
// Prep B: W scaled by 2048, split into fp16 high/low. 4 elems per thread.
// ---------------------------------------------------------------------------
__global__ __launch_bounds__(256)
void prep_b(const float* __restrict__ W) {
    size_t i = ((size_t)blockIdx.x * 256 + threadIdx.x) * 4;
    float4 v = *(const float4*)(W + i);
    float sc[4] = {v.x * 2048.0f, v.y * 2048.0f, v.z * 2048.0f, v.w * 2048.0f};
    __half h[4], l[4];
    #pragma unroll
    for (int j = 0; j < 4; j++) {
        h[j] = __float2half_rn(sc[j]);
        l[j] = __float2half_rn(sc[j] - __half2float(h[j]));
    }
    *(uint2*)(g_bh + i) = *(uint2*)h;
    *(uint2*)(g_bl + i) = *(uint2*)l;
}

// ---------------------------------------------------------------------------
// GEMM chunk: Wx[m,n] = (xh.wh' + xh.wl' + xl.wh') / 2048  (w' = 2048*W)
// Identical to the validated R5 kernel, plus m-tile offset (batch group).
// ---------------------------------------------------------------------------
#define NST 3
#define ASTRIDE 40                     // floats per A smem row (pad 32->40)
#define ABYTES  (128 * ASTRIDE * 4)    // 20480
#define BBYTES  16384                  // bh 8KB + bl 8KB
#define STAGE   (ABYTES + BBYTES)      // 36864
#define GSMEM   (NST * STAGE)          // 110592

__global__ __launch_bounds__(256, 2)
void gemm_mma(const float* __restrict__ X, int my0) {
    extern __shared__ char sm[];
    const uint32_t sbase = smem_u32(sm);
    const int tid  = threadIdx.x;
    const int lane = tid & 31;
    const int warp = tid >> 5;
    const int wm = warp & 3;
    const int wn = warp >> 2;
    const int m0 = (my0 + blockIdx.y) * 128;
    const int n0 = blockIdx.x * 128;

    const int ar  = tid >> 1;
    const int ac0 = (tid & 1) * 4;
    const float* asrc0 = X + (size_t)(m0 + ar) * II + ac0 * 4;
    const uint32_t adst0 = sbase + (uint32_t)(ar * ASTRIDE * 4 + ac0 * 16);

    const int bsel    = tid >> 7;
    const int brow_ld = tid & 127;
    const __half* bsrc = (bsel ? g_bl : g_bh) + (size_t)(n0 + brow_ld) * II;
    const uint32_t bdst = sbase + (uint32_t)(ABYTES + bsel * 8192 + brow_ld * 64);
    const int bxor = (brow_ld >> 1) & 3;

    auto issue = [&](int it) {
        const uint32_t stoff = (uint32_t)(it % NST) * STAGE;
        const float* as = asrc0 + it * 32;
        #pragma unroll
        for (int c = 0; c < 4; c++)
            cp16(adst0 + stoff + c * 16, as + c * 4);
        const __half* bs = bsrc + it * 32;
        #pragma unroll
        for (int ch = 0; ch < 4; ch++)
            cp16(bdst + stoff + (uint32_t)((ch ^ bxor) * 16), bs + ch * 8);
        asm volatile("cp.async.commit_group;");
    };

    issue(0);
    issue(1);

    const int arow0 = wm * 32 + (lane >> 2);
    const int acol0 = (lane & 3) * 2;
    const int brow = wn * 64 + ((lane >> 4) << 3) + (lane & 7);
    const int bch  = (lane >> 3) & 1;

    float acc[2][8][4];
    #pragma unroll
    for (int i = 0; i < 2; i++)
        #pragma unroll
        for (int j = 0; j < 8; j++)
            #pragma unroll
            for (int q = 0; q < 4; q++) acc[i][j][q] = 0.0f;

    for (int it = 0; it < 16; it++) {
        asm volatile("cp.async.wait_group %0;" :: "n"(1));
        __syncthreads();
        if (it + 2 < 16) issue(it + 2);
        else             asm volatile("cp.async.commit_group;");

        const uint32_t stoff = (uint32_t)(it % NST) * STAGE;
        const float*  As32 = (const float*)(sm + stoff);
        const uint32_t Bs  = sbase + stoff + ABYTES;

        #pragma unroll
        for (int kk = 0; kk < 2; kk++) {
            uint32_t ah[2][4], al[2][4];
            #pragma unroll
            for (int mi = 0; mi < 2; mi++) {
                #pragma unroll
                for (int j = 0; j < 4; j++) {
                    const int row = arow0 + mi * 16 + (j & 1) * 8;
                    const int col = acol0 + kk * 16 + (j >> 1) * 8;
                    const float2 f = *(const float2*)(As32 + row * ASTRIDE + col);
                    __half2 h  = __float22half2_rn(f);
                    float2  hf = __half22float2(h);
                    __half2 l  = __floats2half2_rn(f.x - hf.x, f.y - hf.y);
                    ah[mi][j] = h2bits(h);
                    al[mi][j] = h2bits(l);
                }
            }

            uint32_t b[4][4];
            #pragma unroll
            for (int g = 0; g < 4; g++) {
                const int row = brow + g * 16;
                ldsm_x4(b[g], Bs + row * 64 + (((kk * 2 + bch) ^ ((row >> 1) & 3)) * 16));
            }
            #pragma unroll
            for (int mi = 0; mi < 2; mi++)
                #pragma unroll
                for (int nj = 0; nj < 8; nj++)
                    mma16816(acc[mi][nj], ah[mi], b[nj >> 1][(nj & 1) * 2],
                             b[nj >> 1][(nj & 1) * 2 + 1]);
            #pragma unroll
            for (int mi = 0; mi < 2; mi++)
                #pragma unroll
                for (int nj = 0; nj < 8; nj++)
                    mma16816(acc[mi][nj], al[mi], b[nj >> 1][(nj & 1) * 2],
                             b[nj >> 1][(nj & 1) * 2 + 1]);
            #pragma unroll
            for (int g = 0; g < 4; g++) {
                const int row = brow + g * 16;
                ldsm_x4(b[g], Bs + 8192 + row * 64 + (((kk * 2 + bch) ^ ((row >> 1) & 3)) * 16));
            }
            #pragma unroll
            for (int mi = 0; mi < 2; mi++)
                #pragma unroll
                for (int nj = 0; nj < 8; nj++)
                    mma16816(acc[mi][nj], ah[mi], b[nj >> 1][(nj & 1) * 2],
                             b[nj >> 1][(nj & 1) * 2 + 1]);
        }
    }

    const float inv = 1.0f / 2048.0f;
    #pragma unroll
    for (int mi = 0; mi < 2; mi++) {
        const int rr = m0 + wm * 32 + mi * 16 + (lane >> 2);
        #pragma unroll
        for (int nj = 0; nj < 8; nj++) {
            const int cc = n0 + wn * 64 + nj * 8 + 2 * (lane & 3);
            float* p0 = g_wx + (size_t)rr * HH + cc;
            float* p1 = g_wx + (size_t)(rr + 8) * HH + cc;
            *(float2*)p0 = make_float2(acc[mi][nj][0] * inv, acc[mi][nj][1] * inv);
            *(float2*)p1 = make_float2(acc[mi][nj][2] * inv, acc[mi][nj][3] * inv);
        }
    }
}

// ---------------------------------------------------------------------------
// LIF scan chunk (R5 smem-pipeline version + batch offset).
// CTA owns (b, 32 h-lanes); cp.async 64t x 32h chunks; warp 0 scans.
// ---------------------------------------------------------------------------
#define SC_TC   64
#define SC_NH   32
#define SC_CHB  (SC_TC * SC_NH * 4)

__global__ __launch_bounds__(128)
void lif_scan(const float* __restrict__ alpha,
              const float* __restrict__ u0,
              const float* __restrict__ s0,
              float* __restrict__ out, int b0) {
    __shared__ float ws[3][SC_TC][SC_NH];
    const uint32_t sbase = smem_u32(ws);
    const int tid = threadIdx.x;
    const int b   = b0 + (blockIdx.x >> 4);
    const int h0  = (blockIdx.x & 15) * SC_NH;

    const float* src = g_wx + (size_t)b * TT * HH + h0;

    const int lr  = tid >> 1;
    const int lc0 = (tid & 1) * 4;
    const float* lsrc0 = src + (size_t)lr * HH + lc0 * 4;
    const uint32_t ldst0 = sbase + (uint32_t)(lr * SC_NH * 4 + lc0 * 16);

    auto issue = [&](int c) {
        const uint32_t stoff = (uint32_t)(c % 3) * SC_CHB;
        const float* s = lsrc0 + (size_t)(c * SC_TC) * HH;
        #pragma unroll
        for (int i = 0; i < 4; i++)
            cp16(ldst0 + stoff + i * 16, s + i * 4);
        asm volatile("cp.async.commit_group;");
    };

    issue(0);
    issue(1);

    float u = 0.0f, s = 0.0f, al = 0.0f, ial = 0.0f;
    float* q = out;
    if (tid < SC_NH) {
        const int h = h0 + tid;
        al = alpha[h];
        al = fminf(fmaxf(al, ALPHA_LO), ALPHA_HI);
        ial = 1.0f - al;
        u = u0[b * HH + h];
        s = s0[b * HH + h];
        q = out + (size_t)b * TT * HH + h;
    }

    for (int c = 0; c < TT / SC_TC; c++) {
        asm volatile("cp.async.wait_group %0;" :: "n"(1));
        __syncthreads();
        if (c + 2 < TT / SC_TC) issue(c + 2);
        else                    asm volatile("cp.async.commit_group;");

        if (tid < SC_NH) {
            const int st = c % 3;
            const size_t tb = (size_t)(c * SC_TC) * HH;
            #pragma unroll 1
            for (int t8 = 0; t8 < SC_TC; t8 += 8) {
                float w[8];
                #pragma unroll
                for (int j = 0; j < 8; j++) w[j] = ws[st][t8 + j][tid];
                #pragma unroll
                for (int j = 0; j < 8; j++) {
                    u = fmaf(al, u - s, ial * w[j]);
                    s = (u - 1.0f > 0.0f) ? 1.0f : 0.0f;
                    q[tb + (size_t)(t8 + j) * HH] = s;
                }
            }
        }
        __syncthreads();
    }
}

// ---------------------------------------------------------------------------
// Launcher: fork-join pipeline. GEMM chunks on the origin stream; each chunk's
// scan runs on a second stream, overlapping the next GEMM chunk.
// ---------------------------------------------------------------------------
extern "C" void kernel_launch(void* const* d_in, const int* in_sizes, int n_in,
                              void* d_out, int out_size) {
    const float* x     = (const float*)d_in[0];  // [B,T,I]
    const float* W     = (const float*)d_in[1];  // [H,I]
    const float* alpha = (const float*)d_in[2];  // [H]
    const float* u0    = (const float*)d_in[3];  // [B,H]
    const float* s0    = (const float*)d_in[4];  // [B,H]
    float* out = (float*)d_out;                  // [B,T,H]

    static cudaStream_t s2;
    static cudaEvent_t  evg[NGROUP], evj;
    static bool init_done = false;
    if (!init_done) {
        cudaFuncSetAttribute(gemm_mma, cudaFuncAttributeMaxDynamicSharedMemorySize, GSMEM);
        cudaStreamCreateWithFlags(&s2, cudaStreamNonBlocking);
        for (int g = 0; g < NGROUP; g++)
            cudaEventCreateWithFlags(&evg[g], cudaEventDisableTiming);
        cudaEventCreateWithFlags(&evj, cudaEventDisableTiming);
        init_done = true;
    }

    prep_b<<<(int)(((size_t)HH * II) / 4 / 256), 256>>>(W);

    dim3 ggrid(HH / 128, GMT);                   // (4, 64) per chunk
    for (int g = 0; g < NGROUP; g++) {
        gemm_mma<<<ggrid, 256, GSMEM>>>(x, g * GMT);
        cudaEventRecord(evg[g], 0);
        cudaStreamWaitEvent(s2, evg[g], 0);
        lif_scan<<<GB * (HH / SC_NH), 128, 0, s2>>>(alpha, u0, s0, out, g * GB);
    }
    cudaEventRecord(evj, s2);
    cudaStreamWaitEvent(0, evj, 0);
}

// round 7
// speedup vs baseline: 1.5787x; 1.5787x over previous
#include <cuda_runtime.h>
#include <cuda_fp16.h>
#include <cstdint>

#define BB 64
#define TT 1024
#define II 512
#define HH 512
#define MM (BB*TT)              // 65536

#define ALPHA_LO 0.8187307530779818f   // exp(-1/5)
#define ALPHA_HI 0.9607894391523232f   // exp(-1/25)

// Device-global scratch (allocation-guard safe)
__device__ float  g_wx[(size_t)MM * HH];        // 128 MB
__device__ __half g_ah[(size_t)MM * II];        // 64 MB  x high half
__device__ __half g_al[(size_t)MM * II];        // 64 MB  x low  half
__device__ __half g_bh[(size_t)HH * II];        // 512 KB (2048*W) high
__device__ __half g_bl[(size_t)HH * II];        // 512 KB (2048*W) low

// ---------------------------------------------------------------------------
__device__ __forceinline__ uint32_t smem_u32(const void* p) {
    uint32_t a;
    asm("{ .reg .u64 t; cvta.to.shared.u64 t, %1; cvt.u32.u64 %0, t; }" : "=r"(a) : "l"(p));
    return a;
}
__device__ __forceinline__ void cp16(uint32_t dst, const void* src) {
    asm volatile("cp.async.cg.shared.global [%0], [%1], 16;" :: "r"(dst), "l"(src));
}
__device__ __forceinline__ void ldsm_x4(uint32_t* r, uint32_t addr) {
    asm volatile("ldmatrix.sync.aligned.m8n8.x4.shared.b16 {%0,%1,%2,%3}, [%4];"
                 : "=r"(r[0]), "=r"(r[1]), "=r"(r[2]), "=r"(r[3]) : "r"(addr));
}
__device__ __forceinline__ void mma16816(float* c, const uint32_t* a, uint32_t b0, uint32_t b1) {
    asm volatile(
        "mma.sync.aligned.m16n8k16.row.col.f32.f16.f16.f32 "
        "{%0,%1,%2,%3}, {%4,%5,%6,%7}, {%8,%9}, {%0,%1,%2,%3};"
        : "+f"(c[0]), "+f"(c[1]), "+f"(c[2]), "+f"(c[3])
        : "r"(a[0]), "r"(a[1]), "r"(a[2]), "r"(a[3]), "r"(b0), "r"(b1));
}

// ---------------------------------------------------------------------------
// Prep A: split x (fp32) into fp16 high/low halves.  8 elems per thread.
// ---------------------------------------------------------------------------
__global__ __launch_bounds__(256)
void prep_a(const float* __restrict__ x) {
    size_t i = ((size_t)blockIdx.x * 256 + threadIdx.x) * 8;
    float4 v0 = *(const float4*)(x + i);
    float4 v1 = *(const float4*)(x + i + 4);
    float v[8] = {v0.x, v0.y, v0.z, v0.w, v1.x, v1.y, v1.z, v1.w};
    __half h[8], l[8];
    #pragma unroll
    for (int j = 0; j < 8; j++) {
        h[j] = __float2half_rn(v[j]);
        l[j] = __float2half_rn(v[j] - __half2float(h[j]));
    }
    *(uint4*)(g_ah + i) = *(uint4*)h;
    *(uint4*)(g_al + i) = *(uint4*)l;
}

// Prep B: W scaled by 2048, split into fp16 high/low. 4 elems per thread.
__global__ __launch_bounds__(256)
void prep_b(const float* __restrict__ W) {
    size_t i = ((size_t)blockIdx.x * 256 + threadIdx.x) * 4;
    float4 v = *(const float4*)(W + i);
    float s[4] = {v.x * 2048.0f, v.y * 2048.0f, v.z * 2048.0f, v.w * 2048.0f};
    __half h[4], l[4];
    #pragma unroll
    for (int j = 0; j < 4; j++) {
        h[j] = __float2half_rn(s[j]);
        l[j] = __float2half_rn(s[j] - __half2float(h[j]));
    }
    *(uint2*)(g_bh + i) = *(uint2*)h;
    *(uint2*)(g_bl + i) = *(uint2*)l;
}

// ---------------------------------------------------------------------------
// GEMM (R3-exact): Wx[m,n] = (xh.wh' + xh.wl' + xl.wh') / 2048
// CTA tile 128x128, BK=32, 8 warps (4m x 2n), warp tile 32x64.
// 48 k-chunks: seg0 (ah,bh) seg1 (ah,bl) seg2 (al,bh), 16 chunks each.
// 4-stage cp.async pipeline; smem stage = A 8KB + B 8KB.
// ---------------------------------------------------------------------------
#define BK 32
#define NST 4
#define STAGE 16384
#define NCHUNK 48

__global__ __launch_bounds__(256, 2)
void gemm_mma(void) {
    extern __shared__ char sm[];
    const uint32_t sbase = smem_u32(sm);
    const int tid  = threadIdx.x;
    const int lane = tid & 31;
    const int warp = tid >> 5;
    const int wm = warp & 3;
    const int wn = warp >> 2;
    const int m0 = blockIdx.y * 128;
    const int n0 = blockIdx.x * 128;

    const int r0 = tid >> 2;
    const int ch = tid & 3;
    const int phys = ch ^ ((r0 >> 1) & 3);
    const uint32_t dA0 = (uint32_t)(r0 * 64 + phys * 16);
    const uint32_t dA1 = dA0 + 64 * 64;

    float acc[2][8][4];
    #pragma unroll
    for (int i = 0; i < 2; i++)
        #pragma unroll
        for (int j = 0; j < 8; j++)
            #pragma unroll
            for (int q = 0; q < 4; q++) acc[i][j][q] = 0.0f;

    const int arow = wm * 32 + (lane & 15);
    const int ach  = lane >> 4;
    const int brow = wn * 64 + ((lane >> 4) << 3) + (lane & 7);
    const int bch  = (lane >> 3) & 1;

    auto issue = [&](int it) {
        const int s  = it >> 4;
        const int kc = it & 15;
        const __half* Aseg = (s < 2) ? g_ah : g_al;
        const __half* Bseg = (s == 1) ? g_bl : g_bh;
        const uint32_t stb = sbase + (uint32_t)(it & (NST - 1)) * STAGE;
        const __half* asrc = Aseg + (size_t)(m0 + r0) * II + kc * BK + ch * 8;
        const __half* bsrc = Bseg + (size_t)(n0 + r0) * II + kc * BK + ch * 8;
        cp16(stb + dA0, asrc);
        cp16(stb + dA1, asrc + (size_t)64 * II);
        cp16(stb + 8192 + dA0, bsrc);
        cp16(stb + 8192 + dA1, bsrc + (size_t)64 * II);
        asm volatile("cp.async.commit_group;");
    };

    #pragma unroll
    for (int it = 0; it < NST - 1; it++) issue(it);

    for (int it = 0; it < NCHUNK; it++) {
        asm volatile("cp.async.wait_group %0;" :: "n"(NST - 2));
        __syncthreads();
        if (it + NST - 1 < NCHUNK) issue(it + NST - 1);

        const uint32_t As = sbase + (uint32_t)(it & (NST - 1)) * STAGE;
        const uint32_t Bs = As + 8192;

        #pragma unroll
        for (int kk = 0; kk < 2; kk++) {
            uint32_t a[2][4];
            #pragma unroll
            for (int mi = 0; mi < 2; mi++) {
                int row = arow + mi * 16;
                int c   = kk * 2 + ach;
                ldsm_x4(a[mi], As + row * 64 + (c ^ ((row >> 1) & 3)) * 16);
            }
            uint32_t b[4][4];
            #pragma unroll
            for (int g = 0; g < 4; g++) {
                int row = brow + g * 16;
                int c   = kk * 2 + bch;
                ldsm_x4(b[g], Bs + row * 64 + (c ^ ((row >> 1) & 3)) * 16);
            }
            #pragma unroll
            for (int mi = 0; mi < 2; mi++)
                #pragma unroll
                for (int nj = 0; nj < 8; nj++)
                    mma16816(acc[mi][nj], a[mi], b[nj >> 1][(nj & 1) * 2],
                             b[nj >> 1][(nj & 1) * 2 + 1]);
        }
    }

    const float inv = 1.0f / 2048.0f;
    #pragma unroll
    for (int mi = 0; mi < 2; mi++) {
        const int r = m0 + wm * 32 + mi * 16 + (lane >> 2);
        #pragma unroll
        for (int nj = 0; nj < 8; nj++) {
            const int c = n0 + wn * 64 + nj * 8 + 2 * (lane & 3);
            float* p0 = g_wx + (size_t)r * HH + c;
            float* p1 = g_wx + (size_t)(r + 8) * HH + c;
            *(float2*)p0 = make_float2(acc[mi][nj][0] * inv, acc[mi][nj][1] * inv);
            *(float2*)p1 = make_float2(acc[mi][nj][2] * inv, acc[mi][nj][3] * inv);
        }
    }
}

// ---------------------------------------------------------------------------
// LIF scan: 1 thread per (b,h), 32-deep static double buffer (4 MB in flight
// chip-wide vs 2 MB before -> past the BW*latency knee), streaming hints.
// ---------------------------------------------------------------------------
__global__ __launch_bounds__(128)
void lif_scan(const float* __restrict__ alpha,
              const float* __restrict__ u0,
              const float* __restrict__ s0,
              float* __restrict__ out) {
    const int g = blockIdx.x * 128 + threadIdx.x;
    const int b = g >> 9;
    const int h = g & 511;

    float al = alpha[h];
    al = fminf(fmaxf(al, ALPHA_LO), ALPHA_HI);
    const float ial = 1.0f - al;

    float u = u0[g];
    float s = s0[g];

    const float* p = g_wx + (size_t)b * TT * HH + h;
    float*       q = out  + (size_t)b * TT * HH + h;

    float wA[32], wB[32];
    #pragma unroll
    for (int j = 0; j < 32; j++) wA[j] = __ldcs(p + (size_t)j * HH);

    #pragma unroll 1
    for (int t = 0; t < TT; t += 64) {
        #pragma unroll
        for (int j = 0; j < 32; j++) wB[j] = __ldcs(p + (size_t)(t + 32 + j) * HH);
        #pragma unroll
        for (int j = 0; j < 32; j++) {
            u = fmaf(al, u - s, ial * wA[j]);
            s = (u - 1.0f > 0.0f) ? 1.0f : 0.0f;
            __stcs(q + (size_t)(t + j) * HH, s);
        }
        if (t + 64 < TT) {
            #pragma unroll
            for (int j = 0; j < 32; j++) wA[j] = __ldcs(p + (size_t)(t + 64 + j) * HH);
        }
        #pragma unroll
        for (int j = 0; j < 32; j++) {
            u = fmaf(al, u - s, ial * wB[j]);
            s = (u - 1.0f > 0.0f) ? 1.0f : 0.0f;
            __stcs(q + (size_t)(t + 32 + j) * HH, s);
        }
    }
}

// ---------------------------------------------------------------------------
extern "C" void kernel_launch(void* const* d_in, const int* in_sizes, int n_in,
                              void* d_out, int out_size) {
    const float* x     = (const float*)d_in[0];  // [B,T,I]
    const float* W     = (const float*)d_in[1];  // [H,I]
    const float* alpha = (const float*)d_in[2];  // [H]
    const float* u0    = (const float*)d_in[3];  // [B,H]
    const float* s0    = (const float*)d_in[4];  // [B,H]
    float* out = (float*)d_out;                  // [B,T,H]

    static bool attr_set = false;
    if (!attr_set) {
        cudaFuncSetAttribute(gemm_mma, cudaFuncAttributeMaxDynamicSharedMemorySize,
                             NST * STAGE);
        attr_set = true;
    }

    prep_a<<<(int)(((size_t)MM * II) / 8 / 256), 256>>>(x);
    prep_b<<<(int)(((size_t)HH * II) / 4 / 256), 256>>>(W);

    dim3 grid(HH / 128, MM / 128);               // (4, 512) = 2048 CTAs
    gemm_mma<<<grid, 256, NST * STAGE>>>();

    lif_scan<<<(BB * HH) / 128, 128>>>(alpha, u0, s0, out);
}

// round 8
// speedup vs baseline: 1.7033x; 1.0789x over previous
#include <cuda_runtime.h>
#include <cuda_fp16.h>
#include <cstdint>

#define BB 64
#define TT 1024
#define II 512
#define HH 512
#define MM (BB*TT)              // 65536

#define ALPHA_LO 0.8187307530779818f   // exp(-1/5)
#define ALPHA_HI 0.9607894391523232f   // exp(-1/25)

// Device-global scratch (allocation-guard safe)
__device__ float  g_wx[(size_t)MM * HH];        // 128 MB
__device__ __half g_ah[(size_t)MM * II];        // 64 MB  x high half
__device__ __half g_al[(size_t)MM * II];        // 64 MB  x low  half
__device__ __half g_bh[(size_t)HH * II];        // 512 KB (2048*W) high
__device__ __half g_bl[(size_t)HH * II];        // 512 KB (2048*W) low

// ---------------------------------------------------------------------------
__device__ __forceinline__ uint32_t smem_u32(const void* p) {
    uint32_t a;
    asm("{ .reg .u64 t; cvta.to.shared.u64 t, %1; cvt.u32.u64 %0, t; }" : "=r"(a) : "l"(p));
    return a;
}
__device__ __forceinline__ void cp16(uint32_t dst, const void* src) {
    asm volatile("cp.async.cg.shared.global [%0], [%1], 16;" :: "r"(dst), "l"(src));
}
__device__ __forceinline__ void ldsm_x4(uint32_t* r, uint32_t addr) {
    asm volatile("ldmatrix.sync.aligned.m8n8.x4.shared.b16 {%0,%1,%2,%3}, [%4];"
                 : "=r"(r[0]), "=r"(r[1]), "=r"(r[2]), "=r"(r[3]) : "r"(addr));
}
__device__ __forceinline__ void mma16816(float* c, const uint32_t* a, uint32_t b0, uint32_t b1) {
    asm volatile(
        "mma.sync.aligned.m16n8k16.row.col.f32.f16.f16.f32 "
        "{%0,%1,%2,%3}, {%4,%5,%6,%7}, {%8,%9}, {%0,%1,%2,%3};"
        : "+f"(c[0]), "+f"(c[1]), "+f"(c[2]), "+f"(c[3])
        : "r"(a[0]), "r"(a[1]), "r"(a[2]), "r"(a[3]), "r"(b0), "r"(b1));
}

// ---------------------------------------------------------------------------
// Prep A: split x (fp32) into fp16 high/low halves.  8 elems per thread.
// ---------------------------------------------------------------------------
__global__ __launch_bounds__(256)
void prep_a(const float* __restrict__ x) {
    size_t i = ((size_t)blockIdx.x * 256 + threadIdx.x) * 8;
    float4 v0 = *(const float4*)(x + i);
    float4 v1 = *(const float4*)(x + i + 4);
    float v[8] = {v0.x, v0.y, v0.z, v0.w, v1.x, v1.y, v1.z, v1.w};
    __half h[8], l[8];
    #pragma unroll
    for (int j = 0; j < 8; j++) {
        h[j] = __float2half_rn(v[j]);
        l[j] = __float2half_rn(v[j] - __half2float(h[j]));
    }
    *(uint4*)(g_ah + i) = *(uint4*)h;
    *(uint4*)(g_al + i) = *(uint4*)l;
}

// Prep B: W scaled by 2048, split into fp16 high/low. 4 elems per thread.
__global__ __launch_bounds__(256)
void prep_b(const float* __restrict__ W) {
    size_t i = ((size_t)blockIdx.x * 256 + threadIdx.x) * 4;
    float4 v = *(const float4*)(W + i);
    float s[4] = {v.x * 2048.0f, v.y * 2048.0f, v.z * 2048.0f, v.w * 2048.0f};
    __half h[4], l[4];
    #pragma unroll
    for (int j = 0; j < 4; j++) {
        h[j] = __float2half_rn(s[j]);
        l[j] = __float2half_rn(s[j] - __half2float(h[j]));
    }
    *(uint2*)(g_bh + i) = *(uint2*)h;
    *(uint2*)(g_bl + i) = *(uint2*)l;
}

// ---------------------------------------------------------------------------
// GEMM: Wx[m,n] = (xh.wh' + xh.wl' + xl.wh') / 2048  (w' = 2048*W)
// Product-fused chunks: each of 16 k-chunks stages {ah, al, bh, bl} ONCE
// (32KB stage) and runs all 3 products against it. vs R3: -33% cp.async
// fill, -33% LDSM (bh frags reused for ah&al products), -2x A L2 reads,
// same MMA count. CTA 128x128, 8 warps (4m x 2n), 3-stage pipeline.
// ---------------------------------------------------------------------------
#define BK 32
#define NST 3
#define STAGE 32768       // ah 8K | al 8K | bh 8K | bl 8K
#define NCHUNK 16

__global__ __launch_bounds__(256, 2)
void gemm_mma(void) {
    extern __shared__ char sm[];
    const uint32_t sbase = smem_u32(sm);
    const int tid  = threadIdx.x;
    const int lane = tid & 31;
    const int warp = tid >> 5;
    const int wm = warp & 3;
    const int wn = warp >> 2;
    const int m0 = blockIdx.y * 128;
    const int n0 = blockIdx.x * 128;

    // cp.async mapping (R3-proven): rows r0, r0+64, 16B chunk ch, per matrix
    const int r0 = tid >> 2;
    const int ch = tid & 3;
    const int phys = ch ^ ((r0 >> 1) & 3);
    const uint32_t d0 = (uint32_t)(r0 * 64 + phys * 16);
    const uint32_t d1 = d0 + 64 * 64;

    float acc[2][8][4];
    #pragma unroll
    for (int i = 0; i < 2; i++)
        #pragma unroll
        for (int j = 0; j < 8; j++)
            #pragma unroll
            for (int q = 0; q < 4; q++) acc[i][j][q] = 0.0f;

    const int arow = wm * 32 + (lane & 15);
    const int ach  = lane >> 4;
    const int brow = wn * 64 + ((lane >> 4) << 3) + (lane & 7);
    const int bch  = (lane >> 3) & 1;

    const size_t aoff = (size_t)(m0 + r0) * II + ch * 8;
    const size_t boff = (size_t)(n0 + r0) * II + ch * 8;

    auto issue = [&](int it) {
        const uint32_t stb = sbase + (uint32_t)(it % NST) * STAGE;
        const int kc = it * BK;
        const __half* s;
        s = g_ah + aoff + kc;
        cp16(stb + d0, s);  cp16(stb + d1, s + (size_t)64 * II);
        s = g_al + aoff + kc;
        cp16(stb + 8192 + d0, s);  cp16(stb + 8192 + d1, s + (size_t)64 * II);
        s = g_bh + boff + kc;
        cp16(stb + 16384 + d0, s); cp16(stb + 16384 + d1, s + (size_t)64 * II);
        s = g_bl + boff + kc;
        cp16(stb + 24576 + d0, s); cp16(stb + 24576 + d1, s + (size_t)64 * II);
        asm volatile("cp.async.commit_group;");
    };

    issue(0);
    issue(1);

    for (int it = 0; it < NCHUNK; it++) {
        asm volatile("cp.async.wait_group %0;" :: "n"(1));
        __syncthreads();
        if (it + 2 < NCHUNK) issue(it + 2);
        else                 asm volatile("cp.async.commit_group;");

        const uint32_t St = sbase + (uint32_t)(it % NST) * STAGE;

        #pragma unroll
        for (int kk = 0; kk < 2; kk++) {
            const int c = kk * 2;

            // A fragments: hi and lo
            uint32_t a_h[2][4], a_l[2][4];
            #pragma unroll
            for (int mi = 0; mi < 2; mi++) {
                const int row = arow + mi * 16;
                const uint32_t ro = (uint32_t)(row * 64 + (((c + ach) ^ ((row >> 1) & 3)) * 16));
                ldsm_x4(a_h[mi], St + ro);
                ldsm_x4(a_l[mi], St + 8192 + ro);
            }

            // bh fragments -> used by BOTH ah and al products
            uint32_t b[4][4];
            #pragma unroll
            for (int g = 0; g < 4; g++) {
                const int row = brow + g * 16;
                ldsm_x4(b[g], St + 16384 + row * 64 + (((c + bch) ^ ((row >> 1) & 3)) * 16));
            }
            #pragma unroll
            for (int mi = 0; mi < 2; mi++)
                #pragma unroll
                for (int nj = 0; nj < 8; nj++)
                    mma16816(acc[mi][nj], a_h[mi], b[nj >> 1][(nj & 1) * 2],
                             b[nj >> 1][(nj & 1) * 2 + 1]);
            #pragma unroll
            for (int mi = 0; mi < 2; mi++)
                #pragma unroll
                for (int nj = 0; nj < 8; nj++)
                    mma16816(acc[mi][nj], a_l[mi], b[nj >> 1][(nj & 1) * 2],
                             b[nj >> 1][(nj & 1) * 2 + 1]);

            // bl fragments -> ah product only
            #pragma unroll
            for (int g = 0; g < 4; g++) {
                const int row = brow + g * 16;
                ldsm_x4(b[g], St + 24576 + row * 64 + (((c + bch) ^ ((row >> 1) & 3)) * 16));
            }
            #pragma unroll
            for (int mi = 0; mi < 2; mi++)
                #pragma unroll
                for (int nj = 0; nj < 8; nj++)
                    mma16816(acc[mi][nj], a_h[mi], b[nj >> 1][(nj & 1) * 2],
                             b[nj >> 1][(nj & 1) * 2 + 1]);
        }
    }

    const float inv = 1.0f / 2048.0f;
    #pragma unroll
    for (int mi = 0; mi < 2; mi++) {
        const int r = m0 + wm * 32 + mi * 16 + (lane >> 2);
        #pragma unroll
        for (int nj = 0; nj < 8; nj++) {
            const int c = n0 + wn * 64 + nj * 8 + 2 * (lane & 3);
            float* p0 = g_wx + (size_t)r * HH + c;
            float* p1 = g_wx + (size_t)(r + 8) * HH + c;
            *(float2*)p0 = make_float2(acc[mi][nj][0] * inv, acc[mi][nj][1] * inv);
            *(float2*)p1 = make_float2(acc[mi][nj][2] * inv, acc[mi][nj][3] * inv);
        }
    }
}

// ---------------------------------------------------------------------------
// LIF scan (R7-proven): 1 thread per (b,h), 32-deep static double buffer,
// streaming hints. 49.5us, ~4.4TB/s.
// ---------------------------------------------------------------------------
__global__ __launch_bounds__(128)
void lif_scan(const float* __restrict__ alpha,
              const float* __restrict__ u0,
              const float* __restrict__ s0,
              float* __restrict__ out) {
    const int g = blockIdx.x * 128 + threadIdx.x;
    const int b = g >> 9;
    const int h = g & 511;

    float al = alpha[h];
    al = fminf(fmaxf(al, ALPHA_LO), ALPHA_HI);
    const float ial = 1.0f - al;

    float u = u0[g];
    float s = s0[g];

    const float* p = g_wx + (size_t)b * TT * HH + h;
    float*       q = out  + (size_t)b * TT * HH + h;

    float wA[32], wB[32];
    #pragma unroll
    for (int j = 0; j < 32; j++) wA[j] = __ldcs(p + (size_t)j * HH);

    #pragma unroll 1
    for (int t = 0; t < TT; t += 64) {
        #pragma unroll
        for (int j = 0; j < 32; j++) wB[j] = __ldcs(p + (size_t)(t + 32 + j) * HH);
        #pragma unroll
        for (int j = 0; j < 32; j++) {
            u = fmaf(al, u - s, ial * wA[j]);
            s = (u - 1.0f > 0.0f) ? 1.0f : 0.0f;
            __stcs(q + (size_t)(t + j) * HH, s);
        }
        if (t + 64 < TT) {
            #pragma unroll
            for (int j = 0; j < 32; j++) wA[j] = __ldcs(p + (size_t)(t + 64 + j) * HH);
        }
        #pragma unroll
        for (int j = 0; j < 32; j++) {
            u = fmaf(al, u - s, ial * wB[j]);
            s = (u - 1.0f > 0.0f) ? 1.0f : 0.0f;
            __stcs(q + (size_t)(t + 32 + j) * HH, s);
        }
    }
}

// ---------------------------------------------------------------------------
extern "C" void kernel_launch(void* const* d_in, const int* in_sizes, int n_in,
                              void* d_out, int out_size) {
    const float* x     = (const float*)d_in[0];  // [B,T,I]
    const float* W     = (const float*)d_in[1];  // [H,I]
    const float* alpha = (const float*)d_in[2];  // [H]
    const float* u0    = (const float*)d_in[3];  // [B,H]
    const float* s0    = (const float*)d_in[4];  // [B,H]
    float* out = (float*)d_out;                  // [B,T,H]

    static bool attr_set = false;
    if (!attr_set) {
        cudaFuncSetAttribute(gemm_mma, cudaFuncAttributeMaxDynamicSharedMemorySize,
                             NST * STAGE);
        attr_set = true;
    }

    prep_a<<<(int)(((size_t)MM * II) / 8 / 256), 256>>>(x);
    prep_b<<<(int)(((size_t)HH * II) / 4 / 256), 256>>>(W);

    dim3 grid(HH / 128, MM / 128);               // (4, 512) = 2048 CTAs
    gemm_mma<<<grid, 256, NST * STAGE>>>();

    lif_scan<<<(BB * HH) / 128, 128>>>(alpha, u0, s0, out);
}